// round 10
// baseline (speedup 1.0000x reference)
#include <cuda_runtime.h>
#include <math.h>
#include <stddef.h>
#include <stdint.h>
#include <mma.h>

using namespace nvcuda;

typedef unsigned long long ull;

#define B_ 2
#define L_ 1024
#define D_ 64
#define H_ 8
#define NH_ 512
#define MTOT_ 2048

__device__ float g_q[B_*H_*L_*D_];
__device__ float g_k[B_*H_*L_*D_];
__device__ float g_v[B_*H_*L_*D_];
__device__ float g_ps[B_*H_*L_*L_];
__device__ float g_wo[NH_*D_];

// ---------------- f32x2 helpers (pos kernel) ----------------
__device__ __forceinline__ ull f2_fma(ull a, ull b, ull c) {
    ull d; asm("fma.rn.f32x2 %0, %1, %2, %3;" : "=l"(d) : "l"(a), "l"(b), "l"(c)); return d;
}
__device__ __forceinline__ ull f2_add(ull a, ull b) {
    ull d; asm("add.rn.f32x2 %0, %1, %2;" : "=l"(d) : "l"(a), "l"(b)); return d;
}
__device__ __forceinline__ void f2_up(ull v, float& a, float& b) {
    asm("mov.b64 {%0, %1}, %2;" : "=f"(a), "=f"(b) : "l"(v));
}
__device__ __forceinline__ ull d2a(double d) { return __double_as_longlong(d); }

__device__ __forceinline__ float tf32r(float x) {
    return wmma::__float_to_tf32(x);
}

// ---------------- cp.async helpers ----------------
__device__ __forceinline__ uint32_t s2u32(const void* p) {
    uint32_t a;
    asm("{ .reg .u64 t; cvta.to.shared.u64 t, %1; cvt.u32.u64 %0, t; }" : "=r"(a) : "l"(p));
    return a;
}
__device__ __forceinline__ void cpa16(uint32_t dst, const void* src) {
    asm volatile("cp.async.ca.shared.global [%0], [%1], 16;" :: "r"(dst), "l"(src));
}
#define CPA_COMMIT() asm volatile("cp.async.commit_group;" ::: "memory")
#define CPA_WAIT0()  asm volatile("cp.async.wait_group 0;" ::: "memory")

// ---------------------------------------------------------------------------
__global__ __launch_bounds__(256) void init_out(const float* __restrict__ bo,
                                                float* __restrict__ out)
{
    int idx = blockIdx.x * 256 + threadIdx.x;
    float4 b4 = *(const float4*)&bo[(idx & 15) * 4];
    ((float4*)out)[idx] = b4;
}

__global__ __launch_bounds__(256) void round_wo(const float* __restrict__ Wo)
{
    int idx = blockIdx.x * 256 + threadIdx.x;   // over 8192 float4s
    float4 w = ((const float4*)Wo)[idx];
    ((float4*)g_wo)[idx] = make_float4(tf32r(w.x), tf32r(w.y), tf32r(w.z), tf32r(w.w));
}

// ---------------------------------------------------------------------------
// Phase A: position scores for all heads (f32x2 scalar path)
// ---------------------------------------------------------------------------
__global__ __launch_bounds__(256) void pos_kernel(
        const float* __restrict__ pos, const float* __restrict__ Wp,
        const float* __restrict__ bp)
{
    __shared__ float PIs[64][68];
    __shared__ float PJs[16][68];
    __shared__ float Wps[8][68];
    __shared__ float bps[8];

    const int tid = threadIdx.x;
    const int tx = tid & 15, ty = tid >> 4;
    const int j0 = blockIdx.x * 16;
    const int i0 = blockIdx.y * 64;
    const int b  = blockIdx.z;
    const float* pb = pos + (size_t)b * L_ * D_;

    for (int idx = tid; idx < 1024; idx += 256) {
        int r = idx >> 4, c = (idx & 15) << 2;
        *(float4*)&PIs[r][c] = *(const float4*)&pb[(size_t)(i0 + r) * D_ + c];
    }
    {
        int r = tid >> 4, c = (tid & 15) << 2;
        float4 v = *(const float4*)&pb[(size_t)(j0 + r) * D_ + c];
        v.x = -v.x; v.y = -v.y; v.z = -v.z; v.w = -v.w;
        *(float4*)&PJs[r][c] = v;
    }
    for (int idx = tid; idx < 512; idx += 256) {
        int d = idx >> 3, h = idx & 7;
        Wps[h][d] = Wp[idx];
    }
    if (tid < 8) bps[tid] = bp[tid];
    __syncthreads();

    ull acc[4][8];
    #pragma unroll
    for (int ii = 0; ii < 4; ii++)
        #pragma unroll
        for (int h = 0; h < 8; h++) acc[ii][h] = 0ULL;

    const ull AM = 0x7FFFFFFF7FFFFFFFULL;

    #pragma unroll 2
    for (int d0 = 0; d0 < 64; d0 += 4) {
        ull w0[8], w1[8];
        #pragma unroll
        for (int h = 0; h < 8; h++) {
            double2 wd = *(const double2*)&Wps[h][d0];
            w0[h] = d2a(wd.x); w1[h] = d2a(wd.y);
        }
        double2 pjd = *(const double2*)&PJs[tx][d0];
        ull pj0 = d2a(pjd.x), pj1 = d2a(pjd.y);
        #pragma unroll
        for (int ii = 0; ii < 4; ii++) {
            double2 pid = *(const double2*)&PIs[ty*4 + ii][d0];
            ull a0 = f2_add(d2a(pid.x), pj0) & AM;
            ull a1 = f2_add(d2a(pid.y), pj1) & AM;
            #pragma unroll
            for (int h = 0; h < 8; h++) {
                acc[ii][h] = f2_fma(w0[h], a0, acc[ii][h]);
                acc[ii][h] = f2_fma(w1[h], a1, acc[ii][h]);
            }
        }
    }

    #pragma unroll
    for (int ii = 0; ii < 4; ii++) {
        int i = i0 + ty*4 + ii;
        #pragma unroll
        for (int h = 0; h < 8; h++) {
            float lo, hi; f2_up(acc[ii][h], lo, hi);
            g_ps[((size_t)(b*H_ + h) << 20) + ((size_t)i << 10) + j0 + tx]
                = lo + hi + bps[h];
        }
    }
}

// ---------------------------------------------------------------------------
// Phase B: WMMA tf32 attention, pipelined.
// CTA = (64 i-rows, h, b), 256 threads = 8 warps (4 i-blocks x 2 j-blocks).
// accS initialized from g_ps C-frags; exp in fragment registers; row sums via
// P x ones MMA; K/V cp.async double-buffered; out-proj fused, Wo from gmem.
// ---------------------------------------------------------------------------
#define LDM 68
#define TILE_F (64*LDM)

struct AttnSmem2 {
    float Qs[TILE_F];      // Q (pre-rounded, pre-scaled); reused for l-patch
    float Ks[2][TILE_F];   // K double buffer; Ks[0] reused as result buffer
    float Vs[2][TILE_F];
    float Ss[TILE_F];      // P exchange; epilogue: normalized O
};

typedef wmma::fragment<wmma::matrix_a, 16, 16, 8, wmma::precision::tf32, wmma::row_major> FragA;
typedef wmma::fragment<wmma::matrix_b, 16, 16, 8, wmma::precision::tf32, wmma::col_major> FragBc;
typedef wmma::fragment<wmma::matrix_b, 16, 16, 8, wmma::precision::tf32, wmma::row_major> FragBr;
typedef wmma::fragment<wmma::accumulator, 16, 16, 8, float> FragC;

__device__ __forceinline__ void stage_kv(uint32_t ksm, uint32_t vsm,
        const float* kb, const float* vb, int j0, int tid)
{
    #pragma unroll
    for (int n = 0; n < 4; n++) {
        int idx = tid + n*256;                 // 0..1023: 64 rows x 16 chunks
        int r = idx >> 4, c = idx & 15;
        uint32_t off = (uint32_t)(r*LDM + c*4) * 4u;
        const float* ks = kb + (size_t)(j0 + r) * D_ + c*4;
        const float* vs = vb + (size_t)(j0 + r) * D_ + c*4;
        cpa16(ksm + off, ks);
        cpa16(vsm + off, vs);
    }
}

__global__ __launch_bounds__(256) void attn_wmma(float* __restrict__ out)
{
    extern __shared__ char sraw[];
    AttnSmem2& s = *reinterpret_cast<AttnSmem2*>(sraw);

    const int tid = threadIdx.x;
    const int wid = tid >> 5;
    const int iw = wid >> 1;          // i-block 0..3 (rows iw*16..+16)
    const int jw = wid & 1;           // j-block 0..1 (cols jw*32..+32)
    const int i0 = blockIdx.x * 64;
    const int h  = blockIdx.y;
    const int b  = blockIdx.z;

    const float* qb  = g_q  + (size_t)(b*H_ + h) * L_ * D_;
    const float* kb  = g_k  + (size_t)(b*H_ + h) * L_ * D_;
    const float* vb  = g_v  + (size_t)(b*H_ + h) * L_ * D_;
    const float* psb = g_ps + ((size_t)(b*H_ + h) << 20);

    const uint32_t sbase = s2u32(sraw);
    const uint32_t qsm = sbase;
    const uint32_t ksm0 = sbase + sizeof(float)*TILE_F;
    const uint32_t ksm1 = ksm0 + sizeof(float)*TILE_F;
    const uint32_t vsm0 = ksm1 + sizeof(float)*TILE_F;
    const uint32_t vsm1 = vsm0 + sizeof(float)*TILE_F;

    // Pre-loop: stage Q and K/V(0) via cp.async
    #pragma unroll
    for (int n = 0; n < 4; n++) {
        int idx = tid + n*256;
        int r = idx >> 4, c = idx & 15;
        cpa16(qsm + (uint32_t)(r*LDM + c*4)*4u, qb + (size_t)(i0 + r)*D_ + c*4);
    }
    stage_kv(ksm0, vsm0, kb, vb, 0, tid);
    CPA_COMMIT();

    // ps C-frags for tile 0 (gmem; overlaps cp.async)
    FragC psA[2];
    #pragma unroll
    for (int nn = 0; nn < 2; nn++)
        wmma::load_matrix_sync(psA[nn],
            psb + (size_t)(i0 + iw*16) * L_ + jw*32 + nn*16,
            L_, wmma::mem_row_major);

    FragBr ones;
    wmma::fill_fragment(ones, 1.0f);

    FragC accO[2], accL;
    #pragma unroll
    for (int nn = 0; nn < 2; nn++) wmma::fill_fragment(accO[nn], 0.0f);
    wmma::fill_fragment(accL, 0.0f);

    CPA_WAIT0();
    __syncthreads();

    for (int t = 0; t < 16; t++) {
        const int cur = t & 1;
        const float* kcur = (const float*)(cur ? nullptr : nullptr); // (unused)
        const uint32_t kbuf = cur ? ksm1 : ksm0;
        const uint32_t vbuf = cur ? vsm1 : vsm0;
        float* Kp = cur ? &s.Ks[1][0] : &s.Ks[0][0];
        float* Vp = cur ? &s.Vs[1][0] : &s.Vs[0][0];

        // Issue next tile's K/V into the other buffer (its last readers
        // finished before the tail sync of tile t-1).
        if (t < 15) {
            stage_kv(cur ? ksm0 : ksm1, cur ? vsm0 : vsm1, kb, vb, (t+1)*64, tid);
            CPA_COMMIT();
        }

        // ---- S = ps + Q @ K^T ----
        FragC accS[2];
        #pragma unroll
        for (int nn = 0; nn < 2; nn++) accS[nn] = psA[nn];

        // Prefetch ps for tile t+1 (guarded; overlaps MMA + PV)
        {
            const int tn = (t < 15) ? (t + 1) : t;
            #pragma unroll
            for (int nn = 0; nn < 2; nn++)
                wmma::load_matrix_sync(psA[nn],
                    psb + (size_t)(i0 + iw*16) * L_ + tn*64 + jw*32 + nn*16,
                    L_, wmma::mem_row_major);
        }

        #pragma unroll
        for (int kk = 0; kk < 8; kk++) {
            FragA a;
            wmma::load_matrix_sync(a, &s.Qs[(iw*16)*LDM + kk*8], LDM);
            #pragma unroll
            for (int nn = 0; nn < 2; nn++) {
                FragBc kf;
                wmma::load_matrix_sync(kf, &Kp[(jw*32 + nn*16)*LDM + kk*8], LDM);
                wmma::mma_sync(accS[nn], a, kf, accS[nn]);
            }
        }

        // ---- P = exp(S) in fragment registers (layout-agnostic) ----
        #pragma unroll
        for (int nn = 0; nn < 2; nn++) {
            #pragma unroll
            for (int e = 0; e < 8; e++)
                accS[nn].x[e] = tf32r(__expf(accS[nn].x[e]));
            wmma::store_matrix_sync(&s.Ss[(iw*16)*LDM + jw*32 + nn*16], accS[nn],
                                    LDM, wmma::mem_row_major);
        }
        __syncthreads();   // P visible to all warps

        // ---- O += P @ V ; accL += P @ ones (row sums) ----
        #pragma unroll
        for (int kk = 0; kk < 8; kk++) {
            FragA a;
            wmma::load_matrix_sync(a, &s.Ss[(iw*16)*LDM + kk*8], LDM);
            wmma::mma_sync(accL, a, ones, accL);
            #pragma unroll
            for (int nn = 0; nn < 2; nn++) {
                FragBr vf;
                wmma::load_matrix_sync(vf, &Vp[(kk*8)*LDM + jw*32 + nn*16], LDM);
                wmma::mma_sync(accO[nn], a, vf, accO[nn]);
            }
        }

        if (t < 15) CPA_WAIT0();
        __syncthreads();   // close tile: P reads done, next K/V arrived
    }

    // ---- epilogue ----
    // accO -> Ss; accL (row sums, all 16 cols identical) -> Qs patch
    #pragma unroll
    for (int nn = 0; nn < 2; nn++)
        wmma::store_matrix_sync(&s.Ss[(iw*16)*LDM + jw*32 + nn*16], accO[nn],
                                LDM, wmma::mem_row_major);
    if (jw == 0)
        wmma::store_matrix_sync(&s.Qs[(iw*16)*LDM], accL, LDM, wmma::mem_row_major);
    __syncthreads();

    // normalize rows of Ss by 1/l, tf32-round
    {
        const int erow = tid >> 2, equt = tid & 3;
        const float inv = 1.0f / s.Qs[erow*LDM];
        float* orow = &s.Ss[erow*LDM + equt*16];
        #pragma unroll
        for (int c = 0; c < 16; c++) orow[c] = tf32r(orow[c] * inv);
    }
    __syncthreads();

    // result = O_norm @ Wo_h (B-frags straight from g_wo)
    FragC accR[2];
    #pragma unroll
    for (int nn = 0; nn < 2; nn++) wmma::fill_fragment(accR[nn], 0.0f);
    const float* wo = g_wo + (size_t)(h*64) * D_;
    #pragma unroll
    for (int kk = 0; kk < 8; kk++) {
        FragA a;
        wmma::load_matrix_sync(a, &s.Ss[(iw*16)*LDM + kk*8], LDM);
        #pragma unroll
        for (int nn = 0; nn < 2; nn++) {
            FragBr wf;
            wmma::load_matrix_sync(wf, wo + (size_t)(kk*8)*D_ + jw*32 + nn*16, D_);
            wmma::mma_sync(accR[nn], a, wf, accR[nn]);
        }
    }
    // store into Ks[0] region (long dead) — no sync needed before store
    #pragma unroll
    for (int nn = 0; nn < 2; nn++)
        wmma::store_matrix_sync(&s.Ks[0][(iw*16)*LDM + jw*32 + nn*16], accR[nn],
                                LDM, wmma::mem_row_major);
    __syncthreads();
    {
        const int erow = tid >> 2, equt = tid & 3;
        float* dst = &out[(((size_t)b << 10) + i0 + erow) * D_ + equt*16];
        const float* src = &s.Ks[0][erow*LDM + equt*16];
        #pragma unroll
        for (int c = 0; c < 16; c++) atomicAdd(dst + c, src[c]);
    }
}

// ---------------------------------------------------------------------------
// Merged input projections; outputs pre-rounded to tf32 (q also pre-scaled).
// ---------------------------------------------------------------------------
__global__ __launch_bounds__(256) void proj_kernel(
        const float* __restrict__ q_in, const float* __restrict__ k_in,
        const float* __restrict__ v_in,
        const float* __restrict__ Wq, const float* __restrict__ bq,
        const float* __restrict__ Wk, const float* __restrict__ bk,
        const float* __restrict__ Wv, const float* __restrict__ bv)
{
    __shared__ float As[64][68];
    __shared__ float Ws[64][68];
    const int tid = threadIdx.x;
    const int tx = tid & 15, ty = tid >> 4;
    const int m0 = blockIdx.y * 64, n0 = blockIdx.x * 64;
    const int z = blockIdx.z;

    const float* A    = (z == 0) ? q_in : (z == 1) ? k_in : v_in;
    const float* W    = (z == 0) ? Wq   : (z == 1) ? Wk   : Wv;
    const float* bias = (z == 0) ? bq   : (z == 1) ? bk   : bv;
    float* C          = (z == 0) ? g_q  : (z == 1) ? g_k  : g_v;
    const float sc    = (z == 0) ? 0.125f : 1.0f;

    for (int idx = tid; idx < 1024; idx += 256) {
        int r = idx >> 4, c = (idx & 15) << 2;
        *(float4*)&As[r][c] = *(const float4*)&A[(size_t)(m0 + r) * D_ + c];
        *(float4*)&Ws[r][c] = *(const float4*)&W[(size_t)r * NH_ + n0 + c];
    }
    __syncthreads();

    float acc[4][4] = {};
    #pragma unroll 8
    for (int k = 0; k < 64; k++) {
        float a[4];
        #pragma unroll
        for (int i = 0; i < 4; i++) a[i] = As[ty*4 + i][k];
        float4 w4 = *(float4*)&Ws[k][tx*4];
        float w[4] = {w4.x, w4.y, w4.z, w4.w};
        #pragma unroll
        for (int i = 0; i < 4; i++)
            #pragma unroll
            for (int j = 0; j < 4; j++)
                acc[i][j] += a[i] * w[j];
    }

    #pragma unroll
    for (int i = 0; i < 4; i++) {
        int m = m0 + ty*4 + i;
        int bb = m >> 10;
        int l  = m & (L_ - 1);
        #pragma unroll
        for (int j = 0; j < 4; j++) {
            int n = n0 + tx*4 + j;
            int hh = n >> 6, d = n & 63;
            C[(((size_t)bb * H_ + hh) * L_ + l) * D_ + d]
                = tf32r((acc[i][j] + bias[n]) * sc);
        }
    }
}

// ---------------------------------------------------------------------------
extern "C" void kernel_launch(void* const* d_in, const int* in_sizes, int n_in,
                              void* d_out, int out_size)
{
    const float* query = (const float*)d_in[0];
    const float* key   = (const float*)d_in[1];
    const float* value = (const float*)d_in[2];
    const float* pos   = (const float*)d_in[3];
    const float* Wq    = (const float*)d_in[4];
    const float* bq    = (const float*)d_in[5];
    const float* Wk    = (const float*)d_in[6];
    const float* bk    = (const float*)d_in[7];
    const float* Wv    = (const float*)d_in[8];
    const float* bv    = (const float*)d_in[9];
    const float* Wp    = (const float*)d_in[10];
    const float* bp    = (const float*)d_in[11];
    const float* Wo    = (const float*)d_in[12];
    const float* bo    = (const float*)d_in[13];
    float* out = (float*)d_out;

    // Bias init + Wo pre-round (independent, overlap with pos/proj)
    init_out<<<dim3(MTOT_*D_/4/256), 256>>>(bo, out);
    round_wo<<<dim3(NH_*D_/4/256), 256>>>(Wo);

    // Phase A: position scores
    pos_kernel<<<dim3(L_/16, L_/64, B_), 256>>>(pos, Wp, bp);

    // Input projections (tf32 pre-rounded outputs)
    proj_kernel<<<dim3(NH_/64, MTOT_/64, 3), 256>>>(
        query, key, value, Wq, bq, Wk, bk, Wv, bv);

    // Pipelined WMMA tf32 attention + fused output projection
    cudaFuncSetAttribute(attn_wmma, cudaFuncAttributeMaxDynamicSharedMemorySize,
                         (int)sizeof(AttnSmem2));
    attn_wmma<<<dim3(L_/64, H_, B_), 256, sizeof(AttnSmem2)>>>(out);
}

// round 12
// speedup vs baseline: 1.0801x; 1.0801x over previous
#include <cuda_runtime.h>
#include <math.h>
#include <stddef.h>
#include <stdint.h>
#include <mma.h>

using namespace nvcuda;

typedef unsigned long long ull;

#define B_ 2
#define L_ 1024
#define D_ 64
#define H_ 8
#define NH_ 512
#define MTOT_ 2048

__device__ float g_q[B_*H_*L_*D_];
__device__ float g_k[B_*H_*L_*D_];
__device__ float g_v[B_*H_*L_*D_];
__device__ float g_ps[B_*H_*L_*L_];
__device__ float g_wo[NH_*D_];

// ---------------- f32x2 helpers ----------------
__device__ __forceinline__ ull f2_fma(ull a, ull b, ull c) {
    ull d; asm("fma.rn.f32x2 %0, %1, %2, %3;" : "=l"(d) : "l"(a), "l"(b), "l"(c)); return d;
}
__device__ __forceinline__ ull f2_add(ull a, ull b) {
    ull d; asm("add.rn.f32x2 %0, %1, %2;" : "=l"(d) : "l"(a), "l"(b)); return d;
}
__device__ __forceinline__ void f2_up(ull v, float& a, float& b) {
    asm("mov.b64 {%0, %1}, %2;" : "=f"(a), "=f"(b) : "l"(v));
}
__device__ __forceinline__ ull d2a(double d) { return __double_as_longlong(d); }

__device__ __forceinline__ float tf32r(float x) {
    return wmma::__float_to_tf32(x);
}

// ---------------- cp.async helpers ----------------
__device__ __forceinline__ uint32_t s2u32(const void* p) {
    uint32_t a;
    asm("{ .reg .u64 t; cvta.to.shared.u64 t, %1; cvt.u32.u64 %0, t; }" : "=r"(a) : "l"(p));
    return a;
}
__device__ __forceinline__ void cpa16(uint32_t dst, const void* src) {
    asm volatile("cp.async.ca.shared.global [%0], [%1], 16;" :: "r"(dst), "l"(src));
}
#define CPA_COMMIT() asm volatile("cp.async.commit_group;" ::: "memory")
#define CPA_WAIT0()  asm volatile("cp.async.wait_group 0;" ::: "memory")

// ---------------------------------------------------------------------------
// Merged prologue: one launch covering init_out / round_wo / proj / pos.
// Segments by blockIdx.x: [0,128) init, [128,160) wo, [160,928) proj, [928,2976) pos
// ---------------------------------------------------------------------------
struct PosSmem  { float PIs[64][68]; float PJs[16][68]; float Wps[8][68]; float bps[8]; };
struct ProjSmem { float As[64][68];  float Ws[64][68]; };

__global__ __launch_bounds__(256) void prep_kernel(
        const float* __restrict__ q_in, const float* __restrict__ k_in,
        const float* __restrict__ v_in, const float* __restrict__ pos,
        const float* __restrict__ Wq, const float* __restrict__ bq,
        const float* __restrict__ Wk, const float* __restrict__ bk,
        const float* __restrict__ Wv, const float* __restrict__ bv,
        const float* __restrict__ Wp, const float* __restrict__ bp,
        const float* __restrict__ Wo, const float* __restrict__ bo,
        float* __restrict__ out)
{
    __shared__ __align__(16) char smem_raw[sizeof(ProjSmem)];
    const int cta = blockIdx.x;
    const int tid = threadIdx.x;

    if (cta < 128) {
        // ---- init_out: out[b,l,n] = bo[n], 32768 float4s ----
        int idx = cta * 256 + tid;
        float4 b4 = *(const float4*)&bo[(idx & 15) * 4];
        ((float4*)out)[idx] = b4;
        return;
    }
    if (cta < 160) {
        // ---- round_wo: g_wo = tf32(Wo), 8192 float4s ----
        int idx = (cta - 128) * 256 + tid;
        float4 w = ((const float4*)Wo)[idx];
        ((float4*)g_wo)[idx] = make_float4(tf32r(w.x), tf32r(w.y), tf32r(w.z), tf32r(w.w));
        return;
    }
    if (cta < 928) {
        // ---- proj: z = 0/1/2 (q/k/v), outputs tf32-rounded (q pre-scaled) ----
        ProjSmem& s = *reinterpret_cast<ProjSmem*>(smem_raw);
        const int pidx = cta - 160;            // 0..767
        const int bx = pidx & 7;               // n-tile (8)
        const int by = (pidx >> 3) & 31;       // m-tile (32)
        const int z  = pidx >> 8;              // 0..2
        const int tx = tid & 15, ty = tid >> 4;
        const int m0 = by * 64, n0 = bx * 64;

        const float* A    = (z == 0) ? q_in : (z == 1) ? k_in : v_in;
        const float* W    = (z == 0) ? Wq   : (z == 1) ? Wk   : Wv;
        const float* bias = (z == 0) ? bq   : (z == 1) ? bk   : bv;
        float* C          = (z == 0) ? g_q  : (z == 1) ? g_k  : g_v;
        const float sc    = (z == 0) ? 0.125f : 1.0f;

        for (int idx = tid; idx < 1024; idx += 256) {
            int r = idx >> 4, c = (idx & 15) << 2;
            *(float4*)&s.As[r][c] = *(const float4*)&A[(size_t)(m0 + r) * D_ + c];
            *(float4*)&s.Ws[r][c] = *(const float4*)&W[(size_t)r * NH_ + n0 + c];
        }
        __syncthreads();

        float acc[4][4] = {};
        #pragma unroll 8
        for (int k = 0; k < 64; k++) {
            float a[4];
            #pragma unroll
            for (int i = 0; i < 4; i++) a[i] = s.As[ty*4 + i][k];
            float4 w4 = *(float4*)&s.Ws[k][tx*4];
            float w[4] = {w4.x, w4.y, w4.z, w4.w};
            #pragma unroll
            for (int i = 0; i < 4; i++)
                #pragma unroll
                for (int j = 0; j < 4; j++)
                    acc[i][j] += a[i] * w[j];
        }

        #pragma unroll
        for (int i = 0; i < 4; i++) {
            int m = m0 + ty*4 + i;
            int bb = m >> 10;
            int l  = m & (L_ - 1);
            #pragma unroll
            for (int j = 0; j < 4; j++) {
                int n = n0 + tx*4 + j;
                int hh = n >> 6, d = n & 63;
                C[(((size_t)bb * H_ + hh) * L_ + l) * D_ + d]
                    = tf32r((acc[i][j] + bias[n]) * sc);
            }
        }
        return;
    }

    // ---- pos: PS[b,h,i,j] for all heads ----
    {
        PosSmem& s = *reinterpret_cast<PosSmem*>(smem_raw);
        const int pidx = cta - 928;            // 0..2047
        const int bx = pidx & 63;              // j-tile (64)
        const int by = (pidx >> 6) & 15;       // i-tile (16)
        const int b  = pidx >> 10;             // 0..1
        const int tx = tid & 15, ty = tid >> 4;
        const int j0 = bx * 16;
        const int i0 = by * 64;
        const float* pb = pos + (size_t)b * L_ * D_;

        for (int idx = tid; idx < 1024; idx += 256) {
            int r = idx >> 4, c = (idx & 15) << 2;
            *(float4*)&s.PIs[r][c] = *(const float4*)&pb[(size_t)(i0 + r) * D_ + c];
        }
        {
            int r = tid >> 4, c = (tid & 15) << 2;
            float4 v = *(const float4*)&pb[(size_t)(j0 + r) * D_ + c];
            v.x = -v.x; v.y = -v.y; v.z = -v.z; v.w = -v.w;
            *(float4*)&s.PJs[r][c] = v;
        }
        for (int idx = tid; idx < 512; idx += 256) {
            int d = idx >> 3, h = idx & 7;
            s.Wps[h][d] = Wp[idx];
        }
        if (tid < 8) s.bps[tid] = bp[tid];
        __syncthreads();

        ull acc[4][8];
        #pragma unroll
        for (int ii = 0; ii < 4; ii++)
            #pragma unroll
            for (int h = 0; h < 8; h++) acc[ii][h] = 0ULL;

        const ull AM = 0x7FFFFFFF7FFFFFFFULL;

        #pragma unroll 2
        for (int d0 = 0; d0 < 64; d0 += 4) {
            ull w0[8], w1[8];
            #pragma unroll
            for (int h = 0; h < 8; h++) {
                double2 wd = *(const double2*)&s.Wps[h][d0];
                w0[h] = d2a(wd.x); w1[h] = d2a(wd.y);
            }
            double2 pjd = *(const double2*)&s.PJs[tx][d0];
            ull pj0 = d2a(pjd.x), pj1 = d2a(pjd.y);
            #pragma unroll
            for (int ii = 0; ii < 4; ii++) {
                double2 pid = *(const double2*)&s.PIs[ty*4 + ii][d0];
                ull a0 = f2_add(d2a(pid.x), pj0) & AM;
                ull a1 = f2_add(d2a(pid.y), pj1) & AM;
                #pragma unroll
                for (int h = 0; h < 8; h++) {
                    acc[ii][h] = f2_fma(w0[h], a0, acc[ii][h]);
                    acc[ii][h] = f2_fma(w1[h], a1, acc[ii][h]);
                }
            }
        }

        #pragma unroll
        for (int ii = 0; ii < 4; ii++) {
            int i = i0 + ty*4 + ii;
            #pragma unroll
            for (int h = 0; h < 8; h++) {
                float lo, hi; f2_up(acc[ii][h], lo, hi);
                g_ps[((size_t)(b*H_ + h) << 20) + ((size_t)i << 10) + j0 + tx]
                    = lo + hi + s.bps[h];
            }
        }
    }
}

// ---------------------------------------------------------------------------
// Attention: R9 structure + cp.async double-buffered K/V; Wo from g_wo (gmem).
// CTA = (64 i-rows, h, b), 256 threads = 8 warps (4 i-blocks x 2 j-blocks).
// ---------------------------------------------------------------------------
#define LDM 72
#define TILE_F (64*LDM)

struct AttnSmemP {
    float Qs[TILE_F];      // Q (pre-rounded, pre-scaled)
    float Ks[2][TILE_F];   // K double buffer; Ks[0] reused as result buffer
    float Vs[2][TILE_F];
    float Ss[TILE_F];      // S -> P -> (epilogue) normalized O
    float l_s[64];
    float red[64][4];
};

typedef wmma::fragment<wmma::matrix_a, 16, 16, 8, wmma::precision::tf32, wmma::row_major> FragA;
typedef wmma::fragment<wmma::matrix_b, 16, 16, 8, wmma::precision::tf32, wmma::col_major> FragBc;
typedef wmma::fragment<wmma::matrix_b, 16, 16, 8, wmma::precision::tf32, wmma::row_major> FragBr;
typedef wmma::fragment<wmma::accumulator, 16, 16, 8, float> FragC;

__device__ __forceinline__ void stage_kv(uint32_t ksm, uint32_t vsm,
        const float* kb, const float* vb, int j0, int tid)
{
    #pragma unroll
    for (int n = 0; n < 4; n++) {
        int idx = tid + n*256;                 // 0..1023: 64 rows x 16 chunks
        int r = idx >> 4, c = idx & 15;
        uint32_t off = (uint32_t)(r*LDM + c*4) * 4u;
        cpa16(ksm + off, kb + (size_t)(j0 + r) * D_ + c*4);
        cpa16(vsm + off, vb + (size_t)(j0 + r) * D_ + c*4);
    }
}

__global__ __launch_bounds__(256, 2) void attn_wmma(float* __restrict__ out)
{
    extern __shared__ char sraw[];
    AttnSmemP& s = *reinterpret_cast<AttnSmemP*>(sraw);

    const int tid = threadIdx.x;
    const int wid = tid >> 5;
    const int iw = wid >> 1;          // i-block 0..3 (rows iw*16..+16)
    const int jw = wid & 1;           // j-block 0..1 (cols jw*32..+32)
    const int i0 = blockIdx.x * 64;
    const int h  = blockIdx.y;
    const int b  = blockIdx.z;

    const float* qb  = g_q  + (size_t)(b*H_ + h) * L_ * D_;
    const float* kb  = g_k  + (size_t)(b*H_ + h) * L_ * D_;
    const float* vb  = g_v  + (size_t)(b*H_ + h) * L_ * D_;
    const float* psb = g_ps + ((size_t)(b*H_ + h) << 20);

    const uint32_t sbase = s2u32(sraw);
    const uint32_t qsm  = sbase + (uint32_t)offsetof(AttnSmemP, Qs);
    const uint32_t ksm0 = sbase + (uint32_t)offsetof(AttnSmemP, Ks);
    const uint32_t ksm1 = ksm0 + sizeof(float)*TILE_F;
    const uint32_t vsm0 = sbase + (uint32_t)offsetof(AttnSmemP, Vs);
    const uint32_t vsm1 = vsm0 + sizeof(float)*TILE_F;

    // exp-phase mapping: each thread owns a quarter of one row
    const int erow = tid >> 2;
    const int equt = tid & 3;

    // Prelude: stage Q and K/V(0) via cp.async
    #pragma unroll
    for (int n = 0; n < 4; n++) {
        int idx = tid + n*256;
        int r = idx >> 4, c = idx & 15;
        cpa16(qsm + (uint32_t)(r*LDM + c*4)*4u, qb + (size_t)(i0 + r)*D_ + c*4);
    }
    stage_kv(ksm0, vsm0, kb, vb, 0, tid);
    CPA_COMMIT();

    if (tid < 64) s.l_s[tid] = 0.0f;

    FragC accO[2];
    #pragma unroll
    for (int nn = 0; nn < 2; nn++) wmma::fill_fragment(accO[nn], 0.0f);

    CPA_WAIT0();
    __syncthreads();

    for (int t = 0; t < 16; t++) {
        const int cur = t & 1;
        const float* Kp = &s.Ks[cur][0];
        const float* Vp = &s.Vs[cur][0];

        // Issue next tile's K/V into the other buffer (last readers finished
        // before tile t-1's tail sync).
        if (t < 15) {
            stage_kv(cur ? ksm0 : ksm1, cur ? vsm0 : vsm1, kb, vb, (t+1)*64, tid);
            CPA_COMMIT();
        }

        // Prefetch this thread's pos-score quarter-row (used after S phase)
        float4 ps4[4];
        {
            const float* psrow = &psb[((size_t)(i0 + erow) << 10) + t*64 + equt*16];
            #pragma unroll
            for (int c = 0; c < 4; c++) ps4[c] = *(const float4*)&psrow[c*4];
        }

        // ---- S = Q @ K^T ----
        FragC accS[2];
        #pragma unroll
        for (int nn = 0; nn < 2; nn++) wmma::fill_fragment(accS[nn], 0.0f);
        #pragma unroll
        for (int kk = 0; kk < 8; kk++) {
            FragA a;
            wmma::load_matrix_sync(a, &s.Qs[(iw*16)*LDM + kk*8], LDM);
            #pragma unroll
            for (int nn = 0; nn < 2; nn++) {
                FragBc kf;
                wmma::load_matrix_sync(kf, &Kp[(jw*32 + nn*16)*LDM + kk*8], LDM);
                wmma::mma_sync(accS[nn], a, kf, accS[nn]);
            }
        }
        #pragma unroll
        for (int nn = 0; nn < 2; nn++)
            wmma::store_matrix_sync(&s.Ss[(iw*16)*LDM + jw*32 + nn*16], accS[nn],
                                    LDM, wmma::mem_row_major);
        __syncthreads();

        // ---- softmax (no max): P = exp(S + ps), quarter-row sums ----
        {
            float* srow = &s.Ss[erow*LDM + equt*16];
            float sum = 0.0f;
            #pragma unroll
            for (int c = 0; c < 16; c += 4) {
                float4 pv = ps4[c >> 2];
                float p0 = __expf(srow[c+0] + pv.x);
                float p1 = __expf(srow[c+1] + pv.y);
                float p2 = __expf(srow[c+2] + pv.z);
                float p3 = __expf(srow[c+3] + pv.w);
                sum += (p0 + p1) + (p2 + p3);
                srow[c+0] = tf32r(p0); srow[c+1] = tf32r(p1);
                srow[c+2] = tf32r(p2); srow[c+3] = tf32r(p3);
            }
            s.red[erow][equt] = sum;
        }
        __syncthreads();
        if (tid < 64)
            s.l_s[tid] += (s.red[tid][0] + s.red[tid][1])
                        + (s.red[tid][2] + s.red[tid][3]);

        // ---- O += P @ V ----
        #pragma unroll
        for (int kk = 0; kk < 8; kk++) {
            FragA a;
            wmma::load_matrix_sync(a, &s.Ss[(iw*16)*LDM + kk*8], LDM);
            #pragma unroll
            for (int nn = 0; nn < 2; nn++) {
                FragBr vf;
                wmma::load_matrix_sync(vf, &Vp[(kk*8)*LDM + jw*32 + nn*16], LDM);
                wmma::mma_sync(accO[nn], a, vf, accO[nn]);
            }
        }

        if (t < 15) CPA_WAIT0();
        __syncthreads();   // close tile: P/V reads done, next K/V arrived
    }

    // ---- epilogue: normalized O -> smem, proj vs Wo (gmem frags), atomicAdd ----
    #pragma unroll
    for (int nn = 0; nn < 2; nn++)
        wmma::store_matrix_sync(&s.Ss[(iw*16)*LDM + jw*32 + nn*16], accO[nn],
                                LDM, wmma::mem_row_major);
    __syncthreads();
    {
        const float inv = 1.0f / s.l_s[erow];
        float* orow = &s.Ss[erow*LDM + equt*16];
        #pragma unroll
        for (int c = 0; c < 16; c++) orow[c] = tf32r(orow[c] * inv);
    }
    __syncthreads();

    FragC accR[2];
    #pragma unroll
    for (int nn = 0; nn < 2; nn++) wmma::fill_fragment(accR[nn], 0.0f);
    const float* wo = g_wo + (size_t)(h*64) * D_;
    #pragma unroll
    for (int kk = 0; kk < 8; kk++) {
        FragA a;
        wmma::load_matrix_sync(a, &s.Ss[(iw*16)*LDM + kk*8], LDM);
        #pragma unroll
        for (int nn = 0; nn < 2; nn++) {
            FragBr wf;
            wmma::load_matrix_sync(wf, wo + (size_t)(kk*8)*D_ + jw*32 + nn*16, D_);
            wmma::mma_sync(accR[nn], a, wf, accR[nn]);
        }
    }
    #pragma unroll
    for (int nn = 0; nn < 2; nn++)
        wmma::store_matrix_sync(&s.Ks[0][(iw*16)*LDM + jw*32 + nn*16], accR[nn],
                                LDM, wmma::mem_row_major);
    __syncthreads();
    {
        float* dst = &out[(((size_t)b << 10) + i0 + erow) * D_ + equt*16];
        const float* src = &s.Ks[0][erow*LDM + equt*16];
        #pragma unroll
        for (int c = 0; c < 16; c++) atomicAdd(dst + c, src[c]);
    }
}

// ---------------------------------------------------------------------------
extern "C" void kernel_launch(void* const* d_in, const int* in_sizes, int n_in,
                              void* d_out, int out_size)
{
    const float* query = (const float*)d_in[0];
    const float* key   = (const float*)d_in[1];
    const float* value = (const float*)d_in[2];
    const float* pos   = (const float*)d_in[3];
    const float* Wq    = (const float*)d_in[4];
    const float* bq    = (const float*)d_in[5];
    const float* Wk    = (const float*)d_in[6];
    const float* bk    = (const float*)d_in[7];
    const float* Wv    = (const float*)d_in[8];
    const float* bv    = (const float*)d_in[9];
    const float* Wp    = (const float*)d_in[10];
    const float* bp    = (const float*)d_in[11];
    const float* Wo    = (const float*)d_in[12];
    const float* bo    = (const float*)d_in[13];
    float* out = (float*)d_out;

    // Merged prologue: init_out + round_wo + projections + position scores
    prep_kernel<<<dim3(2976), 256>>>(
        query, key, value, pos, Wq, bq, Wk, bk, Wv, bv, Wp, bp, Wo, bo, out);

    // Pipelined WMMA tf32 attention + fused output projection
    cudaFuncSetAttribute(attn_wmma, cudaFuncAttributeMaxDynamicSharedMemorySize,
                         (int)sizeof(AttnSmemP));
    attn_wmma<<<dim3(L_/64, H_, B_), 256, sizeof(AttnSmemP)>>>(out);
}

// round 13
// speedup vs baseline: 1.1014x; 1.0197x over previous
#include <cuda_runtime.h>
#include <math.h>
#include <stddef.h>
#include <stdint.h>
#include <mma.h>

using namespace nvcuda;

typedef unsigned long long ull;

#define B_ 2
#define L_ 1024
#define D_ 64
#define H_ 8
#define NH_ 512
#define MTOT_ 2048

__device__ float g_q[B_*H_*L_*D_];
__device__ float g_k[B_*H_*L_*D_];
__device__ float g_v[B_*H_*L_*D_];
__device__ float g_ps[B_*H_*L_*L_];
__device__ float g_wo[NH_*D_];

// ---------------- f32x2 helpers ----------------
__device__ __forceinline__ ull f2_fma(ull a, ull b, ull c) {
    ull d; asm("fma.rn.f32x2 %0, %1, %2, %3;" : "=l"(d) : "l"(a), "l"(b), "l"(c)); return d;
}
__device__ __forceinline__ ull f2_add(ull a, ull b) {
    ull d; asm("add.rn.f32x2 %0, %1, %2;" : "=l"(d) : "l"(a), "l"(b)); return d;
}
__device__ __forceinline__ void f2_up(ull v, float& a, float& b) {
    asm("mov.b64 {%0, %1}, %2;" : "=f"(a), "=f"(b) : "l"(v));
}
__device__ __forceinline__ ull d2a(double d) { return __double_as_longlong(d); }

__device__ __forceinline__ float tf32r(float x) {
    return wmma::__float_to_tf32(x);
}

// ---------------- cp.async helpers ----------------
__device__ __forceinline__ uint32_t s2u32(const void* p) {
    uint32_t a;
    asm("{ .reg .u64 t; cvta.to.shared.u64 t, %1; cvt.u32.u64 %0, t; }" : "=r"(a) : "l"(p));
    return a;
}
__device__ __forceinline__ void cpa16(uint32_t dst, const void* src) {
    asm volatile("cp.async.ca.shared.global [%0], [%1], 16;" :: "r"(dst), "l"(src));
}
#define CPA_COMMIT() asm volatile("cp.async.commit_group;" ::: "memory")
#define CPA_WAIT0()  asm volatile("cp.async.wait_group 0;" ::: "memory")

// ---------------------------------------------------------------------------
// Merged prologue (unchanged from R12): init_out / round_wo / proj / pos
// Segments by blockIdx.x: [0,128) init, [128,160) wo, [160,928) proj, [928,2976) pos
// ---------------------------------------------------------------------------
struct PosSmem  { float PIs[64][68]; float PJs[16][68]; float Wps[8][68]; float bps[8]; };
struct ProjSmem { float As[64][68];  float Ws[64][68]; };

__global__ __launch_bounds__(256) void prep_kernel(
        const float* __restrict__ q_in, const float* __restrict__ k_in,
        const float* __restrict__ v_in, const float* __restrict__ pos,
        const float* __restrict__ Wq, const float* __restrict__ bq,
        const float* __restrict__ Wk, const float* __restrict__ bk,
        const float* __restrict__ Wv, const float* __restrict__ bv,
        const float* __restrict__ Wp, const float* __restrict__ bp,
        const float* __restrict__ Wo, const float* __restrict__ bo,
        float* __restrict__ out)
{
    __shared__ __align__(16) char smem_raw[sizeof(ProjSmem)];
    const int cta = blockIdx.x;
    const int tid = threadIdx.x;

    if (cta < 128) {
        int idx = cta * 256 + tid;
        float4 b4 = *(const float4*)&bo[(idx & 15) * 4];
        ((float4*)out)[idx] = b4;
        return;
    }
    if (cta < 160) {
        int idx = (cta - 128) * 256 + tid;
        float4 w = ((const float4*)Wo)[idx];
        ((float4*)g_wo)[idx] = make_float4(tf32r(w.x), tf32r(w.y), tf32r(w.z), tf32r(w.w));
        return;
    }
    if (cta < 928) {
        ProjSmem& s = *reinterpret_cast<ProjSmem*>(smem_raw);
        const int pidx = cta - 160;
        const int bx = pidx & 7;
        const int by = (pidx >> 3) & 31;
        const int z  = pidx >> 8;
        const int tx = tid & 15, ty = tid >> 4;
        const int m0 = by * 64, n0 = bx * 64;

        const float* A    = (z == 0) ? q_in : (z == 1) ? k_in : v_in;
        const float* W    = (z == 0) ? Wq   : (z == 1) ? Wk   : Wv;
        const float* bias = (z == 0) ? bq   : (z == 1) ? bk   : bv;
        float* C          = (z == 0) ? g_q  : (z == 1) ? g_k  : g_v;
        const float sc    = (z == 0) ? 0.125f : 1.0f;

        for (int idx = tid; idx < 1024; idx += 256) {
            int r = idx >> 4, c = (idx & 15) << 2;
            *(float4*)&s.As[r][c] = *(const float4*)&A[(size_t)(m0 + r) * D_ + c];
            *(float4*)&s.Ws[r][c] = *(const float4*)&W[(size_t)r * NH_ + n0 + c];
        }
        __syncthreads();

        float acc[4][4] = {};
        #pragma unroll 8
        for (int k = 0; k < 64; k++) {
            float a[4];
            #pragma unroll
            for (int i = 0; i < 4; i++) a[i] = s.As[ty*4 + i][k];
            float4 w4 = *(float4*)&s.Ws[k][tx*4];
            float w[4] = {w4.x, w4.y, w4.z, w4.w};
            #pragma unroll
            for (int i = 0; i < 4; i++)
                #pragma unroll
                for (int j = 0; j < 4; j++)
                    acc[i][j] += a[i] * w[j];
        }

        #pragma unroll
        for (int i = 0; i < 4; i++) {
            int m = m0 + ty*4 + i;
            int bb = m >> 10;
            int l  = m & (L_ - 1);
            #pragma unroll
            for (int j = 0; j < 4; j++) {
                int n = n0 + tx*4 + j;
                int hh = n >> 6, d = n & 63;
                C[(((size_t)bb * H_ + hh) * L_ + l) * D_ + d]
                    = tf32r((acc[i][j] + bias[n]) * sc);
            }
        }
        return;
    }

    {
        PosSmem& s = *reinterpret_cast<PosSmem*>(smem_raw);
        const int pidx = cta - 928;
        const int bx = pidx & 63;
        const int by = (pidx >> 6) & 15;
        const int b  = pidx >> 10;
        const int tx = tid & 15, ty = tid >> 4;
        const int j0 = bx * 16;
        const int i0 = by * 64;
        const float* pb = pos + (size_t)b * L_ * D_;

        for (int idx = tid; idx < 1024; idx += 256) {
            int r = idx >> 4, c = (idx & 15) << 2;
            *(float4*)&s.PIs[r][c] = *(const float4*)&pb[(size_t)(i0 + r) * D_ + c];
        }
        {
            int r = tid >> 4, c = (tid & 15) << 2;
            float4 v = *(const float4*)&pb[(size_t)(j0 + r) * D_ + c];
            v.x = -v.x; v.y = -v.y; v.z = -v.z; v.w = -v.w;
            *(float4*)&s.PJs[r][c] = v;
        }
        for (int idx = tid; idx < 512; idx += 256) {
            int d = idx >> 3, h = idx & 7;
            s.Wps[h][d] = Wp[idx];
        }
        if (tid < 8) s.bps[tid] = bp[tid];
        __syncthreads();

        ull acc[4][8];
        #pragma unroll
        for (int ii = 0; ii < 4; ii++)
            #pragma unroll
            for (int h = 0; h < 8; h++) acc[ii][h] = 0ULL;

        const ull AM = 0x7FFFFFFF7FFFFFFFULL;

        #pragma unroll 2
        for (int d0 = 0; d0 < 64; d0 += 4) {
            ull w0[8], w1[8];
            #pragma unroll
            for (int h = 0; h < 8; h++) {
                double2 wd = *(const double2*)&s.Wps[h][d0];
                w0[h] = d2a(wd.x); w1[h] = d2a(wd.y);
            }
            double2 pjd = *(const double2*)&s.PJs[tx][d0];
            ull pj0 = d2a(pjd.x), pj1 = d2a(pjd.y);
            #pragma unroll
            for (int ii = 0; ii < 4; ii++) {
                double2 pid = *(const double2*)&s.PIs[ty*4 + ii][d0];
                ull a0 = f2_add(d2a(pid.x), pj0) & AM;
                ull a1 = f2_add(d2a(pid.y), pj1) & AM;
                #pragma unroll
                for (int h = 0; h < 8; h++) {
                    acc[ii][h] = f2_fma(w0[h], a0, acc[ii][h]);
                    acc[ii][h] = f2_fma(w1[h], a1, acc[ii][h]);
                }
            }
        }

        #pragma unroll
        for (int ii = 0; ii < 4; ii++) {
            int i = i0 + ty*4 + ii;
            #pragma unroll
            for (int h = 0; h < 8; h++) {
                float lo, hi; f2_up(acc[ii][h], lo, hi);
                g_ps[((size_t)(b*H_ + h) << 20) + ((size_t)i << 10) + j0 + tx]
                    = lo + hi + s.bps[h];
            }
        }
    }
}

// ---------------------------------------------------------------------------
// Attention v3: warp-autonomous rows. CTA = (128 i-rows, h, b), 8 warps, each
// warp owns 16 FULL rows -> P never crosses warps; ONE CTA barrier per tile
// (K/V double-buffer handoff). Q A-frags live in registers for the whole
// kernel. ps loaded as C-frag init; row sums per-lane + shfl.
// ---------------------------------------------------------------------------
#define LDM 68
#define KV_F (64*LDM)

struct AttnSmemX {
    float Ks[2][KV_F];     // K double buffer (col-major consumed)
    float Vs[2][KV_F];     // V double buffer
    float Ss[128*LDM];     // warp-private P / O / result rows
};

typedef wmma::fragment<wmma::matrix_a, 16, 16, 8, wmma::precision::tf32, wmma::row_major> FragA;
typedef wmma::fragment<wmma::matrix_b, 16, 16, 8, wmma::precision::tf32, wmma::col_major> FragBc;
typedef wmma::fragment<wmma::matrix_b, 16, 16, 8, wmma::precision::tf32, wmma::row_major> FragBr;
typedef wmma::fragment<wmma::accumulator, 16, 16, 8, float> FragC;

__device__ __forceinline__ void stage_kv(uint32_t ksm, uint32_t vsm,
        const float* kb, const float* vb, int j0, int tid)
{
    #pragma unroll
    for (int n = 0; n < 4; n++) {
        int idx = tid + n*256;                 // 0..1023: 64 rows x 16 chunks
        int r = idx >> 4, c = idx & 15;
        uint32_t off = (uint32_t)(r*LDM + c*4) * 4u;
        cpa16(ksm + off, kb + (size_t)(j0 + r) * D_ + c*4);
        cpa16(vsm + off, vb + (size_t)(j0 + r) * D_ + c*4);
    }
}

__global__ __launch_bounds__(256) void attn_wmma(float* __restrict__ out)
{
    extern __shared__ char sraw[];
    AttnSmemX& s = *reinterpret_cast<AttnSmemX*>(sraw);

    const int tid  = threadIdx.x;
    const int wid  = tid >> 5;
    const int lane = tid & 31;
    const int row0 = wid * 16;            // warp's 16 rows within the CTA tile
    const int i0 = blockIdx.x * 128;
    const int h  = blockIdx.y;
    const int b  = blockIdx.z;

    const float* qb  = g_q  + (size_t)(b*H_ + h) * L_ * D_;
    const float* kb  = g_k  + (size_t)(b*H_ + h) * L_ * D_;
    const float* vb  = g_v  + (size_t)(b*H_ + h) * L_ * D_;
    const float* psb = g_ps + ((size_t)(b*H_ + h) << 20);

    const uint32_t sbase = s2u32(sraw);
    const uint32_t ksm0 = sbase + (uint32_t)offsetof(AttnSmemX, Ks);
    const uint32_t ksm1 = ksm0 + sizeof(float)*KV_F;
    const uint32_t vsm0 = sbase + (uint32_t)offsetof(AttnSmemX, Vs);
    const uint32_t vsm1 = vsm0 + sizeof(float)*KV_F;

    // Stage K/V tile 0
    stage_kv(ksm0, vsm0, kb, vb, 0, tid);
    CPA_COMMIT();

    // Q A-fragments: loaded ONCE from gmem (tf32-pre-rounded, pre-scaled)
    FragA qf[8];
    #pragma unroll
    for (int kk = 0; kk < 8; kk++)
        wmma::load_matrix_sync(qf[kk], qb + (size_t)(i0 + row0) * D_ + kk*8, D_);

    FragC accO[4];
    #pragma unroll
    for (int nn = 0; nn < 4; nn++) wmma::fill_fragment(accO[nn], 0.0f);

    float rl = 0.0f;                      // row sum for row (row0 + (lane>>1))
    float* Pw = &s.Ss[row0 * LDM];        // warp-private 16xLDM region
    const int lrow = lane >> 1;           // lane's row within warp tile
    const int lcol = (lane & 1) * 32;     // lane's half-row

    CPA_WAIT0();
    __syncthreads();

    for (int t = 0; t < 16; t++) {
        const int cur = t & 1;
        const float* Kp = &s.Ks[cur][0];
        const float* Vp = &s.Vs[cur][0];

        if (t < 15) {
            stage_kv(cur ? ksm0 : ksm1, cur ? vsm0 : vsm1, kb, vb, (t+1)*64, tid);
            CPA_COMMIT();
        }

        // ---- S = ps + Q @ K^T (ps as C-frag init from gmem) ----
        FragC accS[4];
        #pragma unroll
        for (int nn = 0; nn < 4; nn++)
            wmma::load_matrix_sync(accS[nn],
                psb + (size_t)(i0 + row0) * L_ + t*64 + nn*16,
                L_, wmma::mem_row_major);
        #pragma unroll
        for (int kk = 0; kk < 8; kk++) {
            #pragma unroll
            for (int nn = 0; nn < 4; nn++) {
                FragBc kf;
                wmma::load_matrix_sync(kf, &Kp[(nn*16)*LDM + kk*8], LDM);
                wmma::mma_sync(accS[nn], qf[kk], kf, accS[nn]);
            }
        }

        // ---- P = exp(S) in fragment registers; store warp-private ----
        #pragma unroll
        for (int nn = 0; nn < 4; nn++) {
            #pragma unroll
            for (int e = 0; e < 8; e++)
                accS[nn].x[e] = tf32r(__expf(accS[nn].x[e]));
            wmma::store_matrix_sync(&Pw[nn*16], accS[nn], LDM, wmma::mem_row_major);
        }
        __syncwarp();

        // ---- row sum (lane owns half a row; pair-reduce via shfl) ----
        {
            const float* pr = &Pw[lrow*LDM + lcol];
            float sm = 0.0f;
            #pragma unroll
            for (int c = 0; c < 32; c += 4) {
                float4 p4 = *(const float4*)&pr[c];
                sm += (p4.x + p4.y) + (p4.z + p4.w);
            }
            sm += __shfl_xor_sync(0xffffffffu, sm, 1);
            rl += sm;
        }

        // ---- O += P @ V (A-frags from warp-private P) ----
        #pragma unroll
        for (int kk = 0; kk < 8; kk++) {
            FragA a;
            wmma::load_matrix_sync(a, &Pw[kk*8], LDM);
            #pragma unroll
            for (int nn = 0; nn < 4; nn++) {
                FragBr vf;
                wmma::load_matrix_sync(vf, &Vp[(kk*8)*LDM + nn*16], LDM);
                wmma::mma_sync(accO[nn], a, vf, accO[nn]);
            }
        }

        if (t < 15) CPA_WAIT0();
        __syncthreads();   // single barrier: buffer handoff
    }

    // ---- warp-private epilogue: normalize, project vs Wo, atomicAdd ----
    #pragma unroll
    for (int nn = 0; nn < 4; nn++)
        wmma::store_matrix_sync(&Pw[nn*16], accO[nn], LDM, wmma::mem_row_major);
    __syncwarp();
    {
        const float inv = 1.0f / rl;
        float* orow = &Pw[lrow*LDM + lcol];
        #pragma unroll
        for (int c = 0; c < 32; c++) orow[c] = tf32r(orow[c] * inv);
    }
    __syncwarp();

    FragC accR[4];
    #pragma unroll
    for (int nn = 0; nn < 4; nn++) wmma::fill_fragment(accR[nn], 0.0f);
    const float* wo = g_wo + (size_t)(h*64) * D_;
    #pragma unroll
    for (int kk = 0; kk < 8; kk++) {
        FragA a;
        wmma::load_matrix_sync(a, &Pw[kk*8], LDM);
        #pragma unroll
        for (int nn = 0; nn < 4; nn++) {
            FragBr wf;
            wmma::load_matrix_sync(wf, wo + (size_t)(kk*8)*D_ + nn*16, D_);
            wmma::mma_sync(accR[nn], a, wf, accR[nn]);
        }
    }
    __syncwarp();
    #pragma unroll
    for (int nn = 0; nn < 4; nn++)
        wmma::store_matrix_sync(&Pw[nn*16], accR[nn], LDM, wmma::mem_row_major);
    __syncwarp();
    {
        float* dst = &out[(((size_t)b << 10) + i0 + row0 + lrow) * D_ + lcol];
        const float* src = &Pw[lrow*LDM + lcol];
        #pragma unroll
        for (int c = 0; c < 32; c++) atomicAdd(dst + c, src[c]);
    }
}

// ---------------------------------------------------------------------------
extern "C" void kernel_launch(void* const* d_in, const int* in_sizes, int n_in,
                              void* d_out, int out_size)
{
    const float* query = (const float*)d_in[0];
    const float* key   = (const float*)d_in[1];
    const float* value = (const float*)d_in[2];
    const float* pos   = (const float*)d_in[3];
    const float* Wq    = (const float*)d_in[4];
    const float* bq    = (const float*)d_in[5];
    const float* Wk    = (const float*)d_in[6];
    const float* bk    = (const float*)d_in[7];
    const float* Wv    = (const float*)d_in[8];
    const float* bv    = (const float*)d_in[9];
    const float* Wp    = (const float*)d_in[10];
    const float* bp    = (const float*)d_in[11];
    const float* Wo    = (const float*)d_in[12];
    const float* bo    = (const float*)d_in[13];
    float* out = (float*)d_out;

    // Merged prologue: init_out + round_wo + projections + position scores
    prep_kernel<<<dim3(2976), 256>>>(
        query, key, value, pos, Wq, bq, Wk, bk, Wv, bv, Wp, bp, Wo, bo, out);

    // Warp-autonomous WMMA tf32 attention + fused output projection
    cudaFuncSetAttribute(attn_wmma, cudaFuncAttributeMaxDynamicSharedMemorySize,
                         (int)sizeof(AttnSmemX));
    attn_wmma<<<dim3(L_/128, H_, B_), 256, sizeof(AttnSmemX)>>>(out);
}

// round 14
// speedup vs baseline: 1.1248x; 1.0213x over previous
#include <cuda_runtime.h>
#include <math.h>
#include <stddef.h>
#include <stdint.h>
#include <mma.h>

using namespace nvcuda;

typedef unsigned long long ull;

#define B_ 2
#define L_ 1024
#define D_ 64
#define H_ 8
#define NH_ 512
#define MTOT_ 2048

__device__ float g_q[B_*H_*L_*D_];
__device__ float g_k[B_*H_*L_*D_];
__device__ float g_v[B_*H_*L_*D_];
__device__ float g_ps[B_*H_*L_*L_];
__device__ float g_wo[NH_*D_];

// ---------------- f32x2 helpers ----------------
__device__ __forceinline__ ull f2_fma(ull a, ull b, ull c) {
    ull d; asm("fma.rn.f32x2 %0, %1, %2, %3;" : "=l"(d) : "l"(a), "l"(b), "l"(c)); return d;
}
__device__ __forceinline__ ull f2_add(ull a, ull b) {
    ull d; asm("add.rn.f32x2 %0, %1, %2;" : "=l"(d) : "l"(a), "l"(b)); return d;
}
__device__ __forceinline__ void f2_up(ull v, float& a, float& b) {
    asm("mov.b64 {%0, %1}, %2;" : "=f"(a), "=f"(b) : "l"(v));
}
__device__ __forceinline__ ull d2a(double d) { return __double_as_longlong(d); }

__device__ __forceinline__ float tf32r(float x) {
    return wmma::__float_to_tf32(x);
}

// ---------------- cp.async helpers ----------------
__device__ __forceinline__ uint32_t s2u32(const void* p) {
    uint32_t a;
    asm("{ .reg .u64 t; cvta.to.shared.u64 t, %1; cvt.u32.u64 %0, t; }" : "=r"(a) : "l"(p));
    return a;
}
__device__ __forceinline__ void cpa16(uint32_t dst, const void* src) {
    asm volatile("cp.async.ca.shared.global [%0], [%1], 16;" :: "r"(dst), "l"(src));
}
#define CPA_COMMIT() asm volatile("cp.async.commit_group;" ::: "memory")
#define CPA_WAIT0()  asm volatile("cp.async.wait_group 0;" ::: "memory")

// ---------------------------------------------------------------------------
// Merged prologue (unchanged): init_out / round_wo / proj / pos
// Segments by blockIdx.x: [0,128) init, [128,160) wo, [160,928) proj, [928,2976) pos
// ---------------------------------------------------------------------------
struct PosSmem  { float PIs[64][68]; float PJs[16][68]; float Wps[8][68]; float bps[8]; };
struct ProjSmem { float As[64][68];  float Ws[64][68]; };

__global__ __launch_bounds__(256) void prep_kernel(
        const float* __restrict__ q_in, const float* __restrict__ k_in,
        const float* __restrict__ v_in, const float* __restrict__ pos,
        const float* __restrict__ Wq, const float* __restrict__ bq,
        const float* __restrict__ Wk, const float* __restrict__ bk,
        const float* __restrict__ Wv, const float* __restrict__ bv,
        const float* __restrict__ Wp, const float* __restrict__ bp,
        const float* __restrict__ Wo, const float* __restrict__ bo,
        float* __restrict__ out)
{
    __shared__ __align__(16) char smem_raw[sizeof(ProjSmem)];
    const int cta = blockIdx.x;
    const int tid = threadIdx.x;

    if (cta < 128) {
        int idx = cta * 256 + tid;
        float4 b4 = *(const float4*)&bo[(idx & 15) * 4];
        ((float4*)out)[idx] = b4;
        return;
    }
    if (cta < 160) {
        int idx = (cta - 128) * 256 + tid;
        float4 w = ((const float4*)Wo)[idx];
        ((float4*)g_wo)[idx] = make_float4(tf32r(w.x), tf32r(w.y), tf32r(w.z), tf32r(w.w));
        return;
    }
    if (cta < 928) {
        ProjSmem& s = *reinterpret_cast<ProjSmem*>(smem_raw);
        const int pidx = cta - 160;
        const int bx = pidx & 7;
        const int by = (pidx >> 3) & 31;
        const int z  = pidx >> 8;
        const int tx = tid & 15, ty = tid >> 4;
        const int m0 = by * 64, n0 = bx * 64;

        const float* A    = (z == 0) ? q_in : (z == 1) ? k_in : v_in;
        const float* W    = (z == 0) ? Wq   : (z == 1) ? Wk   : Wv;
        const float* bias = (z == 0) ? bq   : (z == 1) ? bk   : bv;
        float* C          = (z == 0) ? g_q  : (z == 1) ? g_k  : g_v;
        const float sc    = (z == 0) ? 0.125f : 1.0f;

        for (int idx = tid; idx < 1024; idx += 256) {
            int r = idx >> 4, c = (idx & 15) << 2;
            *(float4*)&s.As[r][c] = *(const float4*)&A[(size_t)(m0 + r) * D_ + c];
            *(float4*)&s.Ws[r][c] = *(const float4*)&W[(size_t)r * NH_ + n0 + c];
        }
        __syncthreads();

        float acc[4][4] = {};
        #pragma unroll 8
        for (int k = 0; k < 64; k++) {
            float a[4];
            #pragma unroll
            for (int i = 0; i < 4; i++) a[i] = s.As[ty*4 + i][k];
            float4 w4 = *(float4*)&s.Ws[k][tx*4];
            float w[4] = {w4.x, w4.y, w4.z, w4.w};
            #pragma unroll
            for (int i = 0; i < 4; i++)
                #pragma unroll
                for (int j = 0; j < 4; j++)
                    acc[i][j] += a[i] * w[j];
        }

        #pragma unroll
        for (int i = 0; i < 4; i++) {
            int m = m0 + ty*4 + i;
            int bb = m >> 10;
            int l  = m & (L_ - 1);
            #pragma unroll
            for (int j = 0; j < 4; j++) {
                int n = n0 + tx*4 + j;
                int hh = n >> 6, d = n & 63;
                C[(((size_t)bb * H_ + hh) * L_ + l) * D_ + d]
                    = tf32r((acc[i][j] + bias[n]) * sc);
            }
        }
        return;
    }

    {
        PosSmem& s = *reinterpret_cast<PosSmem*>(smem_raw);
        const int pidx = cta - 928;
        const int bx = pidx & 63;
        const int by = (pidx >> 6) & 15;
        const int b  = pidx >> 10;
        const int tx = tid & 15, ty = tid >> 4;
        const int j0 = bx * 16;
        const int i0 = by * 64;
        const float* pb = pos + (size_t)b * L_ * D_;

        for (int idx = tid; idx < 1024; idx += 256) {
            int r = idx >> 4, c = (idx & 15) << 2;
            *(float4*)&s.PIs[r][c] = *(const float4*)&pb[(size_t)(i0 + r) * D_ + c];
        }
        {
            int r = tid >> 4, c = (tid & 15) << 2;
            float4 v = *(const float4*)&pb[(size_t)(j0 + r) * D_ + c];
            v.x = -v.x; v.y = -v.y; v.z = -v.z; v.w = -v.w;
            *(float4*)&s.PJs[r][c] = v;
        }
        for (int idx = tid; idx < 512; idx += 256) {
            int d = idx >> 3, h = idx & 7;
            s.Wps[h][d] = Wp[idx];
        }
        if (tid < 8) s.bps[tid] = bp[tid];
        __syncthreads();

        ull acc[4][8];
        #pragma unroll
        for (int ii = 0; ii < 4; ii++)
            #pragma unroll
            for (int h = 0; h < 8; h++) acc[ii][h] = 0ULL;

        const ull AM = 0x7FFFFFFF7FFFFFFFULL;

        #pragma unroll 2
        for (int d0 = 0; d0 < 64; d0 += 4) {
            ull w0[8], w1[8];
            #pragma unroll
            for (int h = 0; h < 8; h++) {
                double2 wd = *(const double2*)&s.Wps[h][d0];
                w0[h] = d2a(wd.x); w1[h] = d2a(wd.y);
            }
            double2 pjd = *(const double2*)&s.PJs[tx][d0];
            ull pj0 = d2a(pjd.x), pj1 = d2a(pjd.y);
            #pragma unroll
            for (int ii = 0; ii < 4; ii++) {
                double2 pid = *(const double2*)&s.PIs[ty*4 + ii][d0];
                ull a0 = f2_add(d2a(pid.x), pj0) & AM;
                ull a1 = f2_add(d2a(pid.y), pj1) & AM;
                #pragma unroll
                for (int h = 0; h < 8; h++) {
                    acc[ii][h] = f2_fma(w0[h], a0, acc[ii][h]);
                    acc[ii][h] = f2_fma(w1[h], a1, acc[ii][h]);
                }
            }
        }

        #pragma unroll
        for (int ii = 0; ii < 4; ii++) {
            int i = i0 + ty*4 + ii;
            #pragma unroll
            for (int h = 0; h < 8; h++) {
                float lo, hi; f2_up(acc[ii][h], lo, hi);
                g_ps[((size_t)(b*H_ + h) << 20) + ((size_t)i << 10) + j0 + tx]
                    = lo + hi + s.bps[h];
            }
        }
    }
}

// ---------------------------------------------------------------------------
// Attention v4: warp-autonomous rows + ps through the cp.async pipeline.
// CTA = (128 i-rows, h, b), 8 warps, each warp owns 16 full rows.
// Per tile, cp.async stages K(16KB) + V(16KB) + ps(32KB) one tile ahead;
// accS C-frag init loads ps from smem (LDS, not LDG-at-use).
// ---------------------------------------------------------------------------
#define LDM 68
#define KV_F (64*LDM)
#define PS_F (128*LDM)

struct AttnSmemX {
    float Ks[2][KV_F];     // K double buffer
    float Vs[2][KV_F];     // V double buffer
    float PSs[2][PS_F];    // ps double buffer (128 rows x 64 cols, LDM 68)
    float Ss[PS_F];        // warp-private P / O / result rows
};

typedef wmma::fragment<wmma::matrix_a, 16, 16, 8, wmma::precision::tf32, wmma::row_major> FragA;
typedef wmma::fragment<wmma::matrix_b, 16, 16, 8, wmma::precision::tf32, wmma::col_major> FragBc;
typedef wmma::fragment<wmma::matrix_b, 16, 16, 8, wmma::precision::tf32, wmma::row_major> FragBr;
typedef wmma::fragment<wmma::accumulator, 16, 16, 8, float> FragC;

__device__ __forceinline__ void stage_tile(uint32_t ksm, uint32_t vsm, uint32_t psm,
        const float* kb, const float* vb, const float* ps_t, int j0, int tid)
{
    #pragma unroll
    for (int n = 0; n < 4; n++) {
        int idx = tid + n*256;                 // 0..1023: 64 rows x 16 chunks
        int r = idx >> 4, c = idx & 15;
        uint32_t off = (uint32_t)(r*LDM + c*4) * 4u;
        cpa16(ksm + off, kb + (size_t)(j0 + r) * D_ + c*4);
        cpa16(vsm + off, vb + (size_t)(j0 + r) * D_ + c*4);
    }
    #pragma unroll
    for (int n = 0; n < 8; n++) {
        int idx = tid + n*256;                 // 0..2047: 128 rows x 16 chunks
        int r = idx >> 4, c = idx & 15;
        cpa16(psm + (uint32_t)(r*LDM + c*4)*4u, ps_t + (size_t)r * L_ + c*4);
    }
}

__global__ __launch_bounds__(256) void attn_wmma(float* __restrict__ out)
{
    extern __shared__ char sraw[];
    AttnSmemX& s = *reinterpret_cast<AttnSmemX*>(sraw);

    const int tid  = threadIdx.x;
    const int wid  = tid >> 5;
    const int lane = tid & 31;
    const int row0 = wid * 16;            // warp's 16 rows within the CTA tile
    const int i0 = blockIdx.x * 128;
    const int h  = blockIdx.y;
    const int b  = blockIdx.z;

    const float* qb  = g_q  + (size_t)(b*H_ + h) * L_ * D_;
    const float* kb  = g_k  + (size_t)(b*H_ + h) * L_ * D_;
    const float* vb  = g_v  + (size_t)(b*H_ + h) * L_ * D_;
    const float* psb = g_ps + ((size_t)(b*H_ + h) << 20) + ((size_t)i0 << 10);

    const uint32_t sbase = s2u32(sraw);
    const uint32_t ksm0 = sbase + (uint32_t)offsetof(AttnSmemX, Ks);
    const uint32_t ksm1 = ksm0 + sizeof(float)*KV_F;
    const uint32_t vsm0 = sbase + (uint32_t)offsetof(AttnSmemX, Vs);
    const uint32_t vsm1 = vsm0 + sizeof(float)*KV_F;
    const uint32_t psm0 = sbase + (uint32_t)offsetof(AttnSmemX, PSs);
    const uint32_t psm1 = psm0 + sizeof(float)*PS_F;

    // Stage tile 0 (K, V, ps)
    stage_tile(ksm0, vsm0, psm0, kb, vb, psb, 0, tid);
    CPA_COMMIT();

    // Q A-fragments: loaded ONCE from gmem (tf32-pre-rounded, pre-scaled)
    FragA qf[8];
    #pragma unroll
    for (int kk = 0; kk < 8; kk++)
        wmma::load_matrix_sync(qf[kk], qb + (size_t)(i0 + row0) * D_ + kk*8, D_);

    FragC accO[4];
    #pragma unroll
    for (int nn = 0; nn < 4; nn++) wmma::fill_fragment(accO[nn], 0.0f);

    float rl = 0.0f;                      // row sum for row (row0 + (lane>>1))
    float* Pw = &s.Ss[row0 * LDM];        // warp-private 16xLDM region
    const int lrow = lane >> 1;           // lane's row within warp tile
    const int lcol = (lane & 1) * 32;     // lane's half-row

    CPA_WAIT0();
    __syncthreads();

    for (int t = 0; t < 16; t++) {
        const int cur = t & 1;
        const float* Kp  = &s.Ks[cur][0];
        const float* Vp  = &s.Vs[cur][0];
        const float* PSp = &s.PSs[cur][0];

        if (t < 15) {
            stage_tile(cur ? ksm0 : ksm1, cur ? vsm0 : vsm1, cur ? psm0 : psm1,
                       kb, vb, psb + (t+1)*64, (t+1)*64, tid);
            CPA_COMMIT();
        }

        // ---- S = ps + Q @ K^T (ps C-frag init from SMEM) ----
        FragC accS[4];
        #pragma unroll
        for (int nn = 0; nn < 4; nn++)
            wmma::load_matrix_sync(accS[nn], &PSp[row0*LDM + nn*16],
                                   LDM, wmma::mem_row_major);
        #pragma unroll
        for (int kk = 0; kk < 8; kk++) {
            #pragma unroll
            for (int nn = 0; nn < 4; nn++) {
                FragBc kf;
                wmma::load_matrix_sync(kf, &Kp[(nn*16)*LDM + kk*8], LDM);
                wmma::mma_sync(accS[nn], qf[kk], kf, accS[nn]);
            }
        }

        // ---- P = exp(S) in fragment registers; store warp-private ----
        #pragma unroll
        for (int nn = 0; nn < 4; nn++) {
            #pragma unroll
            for (int e = 0; e < 8; e++)
                accS[nn].x[e] = tf32r(__expf(accS[nn].x[e]));
            wmma::store_matrix_sync(&Pw[nn*16], accS[nn], LDM, wmma::mem_row_major);
        }
        __syncwarp();

        // ---- row sum (lane owns half a row; pair-reduce via shfl) ----
        {
            const float* pr = &Pw[lrow*LDM + lcol];
            float sm = 0.0f;
            #pragma unroll
            for (int c = 0; c < 32; c += 4) {
                float4 p4 = *(const float4*)&pr[c];
                sm += (p4.x + p4.y) + (p4.z + p4.w);
            }
            sm += __shfl_xor_sync(0xffffffffu, sm, 1);
            rl += sm;
        }

        // ---- O += P @ V (A-frags from warp-private P) ----
        #pragma unroll
        for (int kk = 0; kk < 8; kk++) {
            FragA a;
            wmma::load_matrix_sync(a, &Pw[kk*8], LDM);
            #pragma unroll
            for (int nn = 0; nn < 4; nn++) {
                FragBr vf;
                wmma::load_matrix_sync(vf, &Vp[(kk*8)*LDM + nn*16], LDM);
                wmma::mma_sync(accO[nn], a, vf, accO[nn]);
            }
        }

        if (t < 15) CPA_WAIT0();
        __syncthreads();   // single barrier: buffer handoff
    }

    // ---- warp-private epilogue: normalize, project vs Wo, atomicAdd ----
    #pragma unroll
    for (int nn = 0; nn < 4; nn++)
        wmma::store_matrix_sync(&Pw[nn*16], accO[nn], LDM, wmma::mem_row_major);
    __syncwarp();
    {
        const float inv = 1.0f / rl;
        float* orow = &Pw[lrow*LDM + lcol];
        #pragma unroll
        for (int c = 0; c < 32; c++) orow[c] = tf32r(orow[c] * inv);
    }
    __syncwarp();

    FragC accR[4];
    #pragma unroll
    for (int nn = 0; nn < 4; nn++) wmma::fill_fragment(accR[nn], 0.0f);
    const float* wo = g_wo + (size_t)(h*64) * D_;
    #pragma unroll
    for (int kk = 0; kk < 8; kk++) {
        FragA a;
        wmma::load_matrix_sync(a, &Pw[kk*8], LDM);
        #pragma unroll
        for (int nn = 0; nn < 4; nn++) {
            FragBr wf;
            wmma::load_matrix_sync(wf, wo + (size_t)(kk*8)*D_ + nn*16, D_);
            wmma::mma_sync(accR[nn], a, wf, accR[nn]);
        }
    }
    __syncwarp();
    #pragma unroll
    for (int nn = 0; nn < 4; nn++)
        wmma::store_matrix_sync(&Pw[nn*16], accR[nn], LDM, wmma::mem_row_major);
    __syncwarp();
    {
        float* dst = &out[(((size_t)b << 10) + i0 + row0 + lrow) * D_ + lcol];
        const float* src = &Pw[lrow*LDM + lcol];
        #pragma unroll
        for (int c = 0; c < 32; c++) atomicAdd(dst + c, src[c]);
    }
}

// ---------------------------------------------------------------------------
extern "C" void kernel_launch(void* const* d_in, const int* in_sizes, int n_in,
                              void* d_out, int out_size)
{
    const float* query = (const float*)d_in[0];
    const float* key   = (const float*)d_in[1];
    const float* value = (const float*)d_in[2];
    const float* pos   = (const float*)d_in[3];
    const float* Wq    = (const float*)d_in[4];
    const float* bq    = (const float*)d_in[5];
    const float* Wk    = (const float*)d_in[6];
    const float* bk    = (const float*)d_in[7];
    const float* Wv    = (const float*)d_in[8];
    const float* bv    = (const float*)d_in[9];
    const float* Wp    = (const float*)d_in[10];
    const float* bp    = (const float*)d_in[11];
    const float* Wo    = (const float*)d_in[12];
    const float* bo    = (const float*)d_in[13];
    float* out = (float*)d_out;

    // Merged prologue: init_out + round_wo + projections + position scores
    prep_kernel<<<dim3(2976), 256>>>(
        query, key, value, pos, Wq, bq, Wk, bk, Wv, bv, Wp, bp, Wo, bo, out);

    // Warp-autonomous WMMA tf32 attention + async ps/K/V pipeline
    cudaFuncSetAttribute(attn_wmma, cudaFuncAttributeMaxDynamicSharedMemorySize,
                         (int)sizeof(AttnSmemX));
    attn_wmma<<<dim3(L_/128, H_, B_), 256, sizeof(AttnSmemX)>>>(out);
}

// round 16
// speedup vs baseline: 1.6957x; 1.5075x over previous
#include <cuda_runtime.h>
#include <cuda_fp16.h>
#include <math.h>
#include <stddef.h>
#include <stdint.h>
#include <mma.h>

using namespace nvcuda;

typedef unsigned long long ull;

#define B_ 2
#define L_ 1024
#define D_ 64
#define H_ 8
#define NH_ 512
#define MTOT_ 2048

__device__ __half g_q[B_*H_*L_*D_];
__device__ __half g_k[B_*H_*L_*D_];
__device__ __half g_v[B_*H_*L_*D_];
__device__ __half g_ps[B_*H_*L_*L_];
__device__ __half g_wo[NH_*D_];

// ---------------- f32x2 helpers (pos math) ----------------
__device__ __forceinline__ ull f2_fma(ull a, ull b, ull c) {
    ull d; asm("fma.rn.f32x2 %0, %1, %2, %3;" : "=l"(d) : "l"(a), "l"(b), "l"(c)); return d;
}
__device__ __forceinline__ ull f2_add(ull a, ull b) {
    ull d; asm("add.rn.f32x2 %0, %1, %2;" : "=l"(d) : "l"(a), "l"(b)); return d;
}
__device__ __forceinline__ void f2_up(ull v, float& a, float& b) {
    asm("mov.b64 {%0, %1}, %2;" : "=f"(a), "=f"(b) : "l"(v));
}
__device__ __forceinline__ ull d2a(double d) { return __double_as_longlong(d); }

// ---------------- cp.async helpers ----------------
__device__ __forceinline__ uint32_t s2u32(const void* p) {
    uint32_t a;
    asm("{ .reg .u64 t; cvta.to.shared.u64 t, %1; cvt.u32.u64 %0, t; }" : "=r"(a) : "l"(p));
    return a;
}
__device__ __forceinline__ void cpa16(uint32_t dst, const void* src) {
    asm volatile("cp.async.ca.shared.global [%0], [%1], 16;" :: "r"(dst), "l"(src));
}
#define CPA_COMMIT() asm volatile("cp.async.commit_group;" ::: "memory")
#define CPA_WAIT0()  asm volatile("cp.async.wait_group 0;" ::: "memory")

// ---------------------------------------------------------------------------
// Merged prologue: init_out / wo->fp16 / proj(fp16 out) / pos(fp16 out)
// Segments by blockIdx.x: [0,128) init, [128,160) wo, [160,928) proj, [928,2976) pos
// ---------------------------------------------------------------------------
struct PosSmem  { float PIs[64][68]; float PJs[16][68]; float Wps[8][68]; float bps[8]; };
struct ProjSmem { float As[64][68];  float Ws[64][68]; };

__global__ __launch_bounds__(256) void prep_kernel(
        const float* __restrict__ q_in, const float* __restrict__ k_in,
        const float* __restrict__ v_in, const float* __restrict__ pos,
        const float* __restrict__ Wq, const float* __restrict__ bq,
        const float* __restrict__ Wk, const float* __restrict__ bk,
        const float* __restrict__ Wv, const float* __restrict__ bv,
        const float* __restrict__ Wp, const float* __restrict__ bp,
        const float* __restrict__ Wo, const float* __restrict__ bo,
        float* __restrict__ out)
{
    __shared__ __align__(16) char smem_raw[sizeof(ProjSmem)];
    const int cta = blockIdx.x;
    const int tid = threadIdx.x;

    if (cta < 128) {
        int idx = cta * 256 + tid;
        float4 b4 = *(const float4*)&bo[(idx & 15) * 4];
        ((float4*)out)[idx] = b4;
        return;
    }
    if (cta < 160) {
        int idx = (cta - 128) * 256 + tid;   // 0..8191 float4s of Wo
        float4 w = ((const float4*)Wo)[idx];
        __half2* dst = (__half2*)&g_wo[idx * 4];
        dst[0] = __floats2half2_rn(w.x, w.y);
        dst[1] = __floats2half2_rn(w.z, w.w);
        return;
    }
    if (cta < 928) {
        ProjSmem& s = *reinterpret_cast<ProjSmem*>(smem_raw);
        const int pidx = cta - 160;
        const int bx = pidx & 7;
        const int by = (pidx >> 3) & 31;
        const int z  = pidx >> 8;
        const int tx = tid & 15, ty = tid >> 4;
        const int m0 = by * 64, n0 = bx * 64;

        const float* A    = (z == 0) ? q_in : (z == 1) ? k_in : v_in;
        const float* W    = (z == 0) ? Wq   : (z == 1) ? Wk   : Wv;
        const float* bias = (z == 0) ? bq   : (z == 1) ? bk   : bv;
        __half* C         = (z == 0) ? g_q  : (z == 1) ? g_k  : g_v;
        const float sc    = (z == 0) ? 0.125f : 1.0f;

        for (int idx = tid; idx < 1024; idx += 256) {
            int r = idx >> 4, c = (idx & 15) << 2;
            *(float4*)&s.As[r][c] = *(const float4*)&A[(size_t)(m0 + r) * D_ + c];
            *(float4*)&s.Ws[r][c] = *(const float4*)&W[(size_t)r * NH_ + n0 + c];
        }
        __syncthreads();

        float acc[4][4] = {};
        #pragma unroll 8
        for (int k = 0; k < 64; k++) {
            float a[4];
            #pragma unroll
            for (int i = 0; i < 4; i++) a[i] = s.As[ty*4 + i][k];
            float4 w4 = *(float4*)&s.Ws[k][tx*4];
            float w[4] = {w4.x, w4.y, w4.z, w4.w};
            #pragma unroll
            for (int i = 0; i < 4; i++)
                #pragma unroll
                for (int j = 0; j < 4; j++)
                    acc[i][j] += a[i] * w[j];
        }

        #pragma unroll
        for (int i = 0; i < 4; i++) {
            int m = m0 + ty*4 + i;
            int bb = m >> 10;
            int l  = m & (L_ - 1);
            #pragma unroll
            for (int j = 0; j < 4; j++) {
                int n = n0 + tx*4 + j;
                int hh = n >> 6, d = n & 63;
                C[(((size_t)bb * H_ + hh) * L_ + l) * D_ + d]
                    = __float2half_rn((acc[i][j] + bias[n]) * sc);
            }
        }
        return;
    }

    {
        PosSmem& s = *reinterpret_cast<PosSmem*>(smem_raw);
        const int pidx = cta - 928;
        const int bx = pidx & 63;
        const int by = (pidx >> 6) & 15;
        const int b  = pidx >> 10;
        const int tx = tid & 15, ty = tid >> 4;
        const int j0 = bx * 16;
        const int i0 = by * 64;
        const float* pb = pos + (size_t)b * L_ * D_;

        for (int idx = tid; idx < 1024; idx += 256) {
            int r = idx >> 4, c = (idx & 15) << 2;
            *(float4*)&s.PIs[r][c] = *(const float4*)&pb[(size_t)(i0 + r) * D_ + c];
        }
        {
            int r = tid >> 4, c = (tid & 15) << 2;
            float4 v = *(const float4*)&pb[(size_t)(j0 + r) * D_ + c];
            v.x = -v.x; v.y = -v.y; v.z = -v.z; v.w = -v.w;
            *(float4*)&s.PJs[r][c] = v;
        }
        for (int idx = tid; idx < 512; idx += 256) {
            int d = idx >> 3, h = idx & 7;
            s.Wps[h][d] = Wp[idx];
        }
        if (tid < 8) s.bps[tid] = bp[tid];
        __syncthreads();

        ull acc[4][8];
        #pragma unroll
        for (int ii = 0; ii < 4; ii++)
            #pragma unroll
            for (int h = 0; h < 8; h++) acc[ii][h] = 0ULL;

        const ull AM = 0x7FFFFFFF7FFFFFFFULL;

        #pragma unroll 2
        for (int d0 = 0; d0 < 64; d0 += 4) {
            ull w0[8], w1[8];
            #pragma unroll
            for (int h = 0; h < 8; h++) {
                double2 wd = *(const double2*)&s.Wps[h][d0];
                w0[h] = d2a(wd.x); w1[h] = d2a(wd.y);
            }
            double2 pjd = *(const double2*)&s.PJs[tx][d0];
            ull pj0 = d2a(pjd.x), pj1 = d2a(pjd.y);
            #pragma unroll
            for (int ii = 0; ii < 4; ii++) {
                double2 pid = *(const double2*)&s.PIs[ty*4 + ii][d0];
                ull a0 = f2_add(d2a(pid.x), pj0) & AM;
                ull a1 = f2_add(d2a(pid.y), pj1) & AM;
                #pragma unroll
                for (int h = 0; h < 8; h++) {
                    acc[ii][h] = f2_fma(w0[h], a0, acc[ii][h]);
                    acc[ii][h] = f2_fma(w1[h], a1, acc[ii][h]);
                }
            }
        }

        #pragma unroll
        for (int ii = 0; ii < 4; ii++) {
            int i = i0 + ty*4 + ii;
            #pragma unroll
            for (int h = 0; h < 8; h++) {
                float lo, hi; f2_up(acc[ii][h], lo, hi);
                g_ps[((size_t)(b*H_ + h) << 20) + ((size_t)i << 10) + j0 + tx]
                    = __float2half_rn(lo + hi + s.bps[h]);
            }
        }
    }
}

// ---------------------------------------------------------------------------
// Attention v5: fp16 WMMA (m16n16k16), warp-autonomous rows, triple-stream
// cp.async double buffer (K, V, ps all fp16). CTA = (128 i-rows, h, b),
// 8 warps x 16 rows. S accum fp32 -> warp-private smem -> exp+ps -> P fp16.
// ---------------------------------------------------------------------------
#define LDK 72            // half stride (144 B rows)
#define LDS4 68           // float stride for S

#define KV_H (64*LDK)     // halfs per K/V buffer
#define PS_H (128*LDK)    // halfs per ps buffer

struct AttnSmemH {
    __half Ks[2][KV_H];
    __half Vs[2][KV_H];
    __half PSs[2][PS_H];
    float  Ss[128*LDS4];  // S (fp32) / O / result, warp-private rows
    __half Ph[128*LDK];   // P (fp16), warp-private rows
};

typedef wmma::fragment<wmma::matrix_a, 16, 16, 16, __half, wmma::row_major> HFragA;
typedef wmma::fragment<wmma::matrix_b, 16, 16, 16, __half, wmma::col_major> HFragBc;
typedef wmma::fragment<wmma::matrix_b, 16, 16, 16, __half, wmma::row_major> HFragBr;
typedef wmma::fragment<wmma::accumulator, 16, 16, 16, float> HFragC;

__device__ __forceinline__ void stage_tile(uint32_t ksm, uint32_t vsm, uint32_t psm,
        const __half* kb, const __half* vb, const __half* ps_t, int j0, int tid)
{
    // K and V: 64 rows x 8 chunks of 16B (8 halfs)
    #pragma unroll
    for (int n = 0; n < 2; n++) {
        int idx = tid + n*256;                 // 0..511
        int r = idx >> 3, c = idx & 7;
        uint32_t off = (uint32_t)(r*LDK + c*8) * 2u;
        cpa16(ksm + off, kb + (size_t)(j0 + r) * D_ + c*8);
        cpa16(vsm + off, vb + (size_t)(j0 + r) * D_ + c*8);
    }
    // ps: 128 rows x 8 chunks of 16B
    #pragma unroll
    for (int n = 0; n < 4; n++) {
        int idx = tid + n*256;                 // 0..1023
        int r = idx >> 3, c = idx & 7;
        cpa16(psm + (uint32_t)(r*LDK + c*8)*2u, ps_t + (size_t)r * L_ + c*8);
    }
}

__global__ __launch_bounds__(256) void attn_wmma(float* __restrict__ out)
{
    extern __shared__ char sraw[];
    AttnSmemH& s = *reinterpret_cast<AttnSmemH*>(sraw);

    const int tid  = threadIdx.x;
    const int wid  = tid >> 5;
    const int lane = tid & 31;
    const int row0 = wid * 16;            // warp's 16 rows within CTA tile
    const int i0 = blockIdx.x * 128;
    const int h  = blockIdx.y;
    const int b  = blockIdx.z;

    const __half* qb  = g_q  + (size_t)(b*H_ + h) * L_ * D_;
    const __half* kb  = g_k  + (size_t)(b*H_ + h) * L_ * D_;
    const __half* vb  = g_v  + (size_t)(b*H_ + h) * L_ * D_;
    const __half* psb = g_ps + ((size_t)(b*H_ + h) << 20) + ((size_t)i0 << 10);

    const uint32_t sbase = s2u32(sraw);
    const uint32_t ksm0 = sbase + (uint32_t)offsetof(AttnSmemH, Ks);
    const uint32_t ksm1 = ksm0 + sizeof(__half)*KV_H;
    const uint32_t vsm0 = sbase + (uint32_t)offsetof(AttnSmemH, Vs);
    const uint32_t vsm1 = vsm0 + sizeof(__half)*KV_H;
    const uint32_t psm0 = sbase + (uint32_t)offsetof(AttnSmemH, PSs);
    const uint32_t psm1 = psm0 + sizeof(__half)*PS_H;

    // Stage tile 0 (K, V, ps)
    stage_tile(ksm0, vsm0, psm0, kb, vb, psb, 0, tid);
    CPA_COMMIT();

    // Q A-fragments (fp16), loaded once from gmem, pre-scaled by 1/8
    HFragA qf[4];
    #pragma unroll
    for (int kk = 0; kk < 4; kk++)
        wmma::load_matrix_sync(qf[kk], qb + (size_t)(i0 + row0) * D_ + kk*16, D_);

    HFragC accO[4];
    #pragma unroll
    for (int nn = 0; nn < 4; nn++) wmma::fill_fragment(accO[nn], 0.0f);

    float rl = 0.0f;
    float*  Sw = &s.Ss[row0 * LDS4];      // warp-private S (fp32)
    __half* Pw = &s.Ph[row0 * LDK];       // warp-private P (fp16)
    const int lrow = lane >> 1;
    const int lcol = (lane & 1) * 32;

    CPA_WAIT0();
    __syncthreads();

    for (int t = 0; t < 16; t++) {
        const int cur = t & 1;
        const __half* Kp  = &s.Ks[cur][0];
        const __half* Vp  = &s.Vs[cur][0];
        const __half* PSp = &s.PSs[cur][0];

        if (t < 15) {
            stage_tile(cur ? ksm0 : ksm1, cur ? vsm0 : vsm1, cur ? psm0 : psm1,
                       kb, vb, psb + (t+1)*64, (t+1)*64, tid);
            CPA_COMMIT();
        }

        // ---- S = Q @ K^T (fp32 accum) ----
        HFragC accS[4];
        #pragma unroll
        for (int nn = 0; nn < 4; nn++) wmma::fill_fragment(accS[nn], 0.0f);
        #pragma unroll
        for (int kk = 0; kk < 4; kk++) {
            #pragma unroll
            for (int nn = 0; nn < 4; nn++) {
                HFragBc kf;
                wmma::load_matrix_sync(kf, &Kp[(nn*16)*LDK + kk*16], LDK);
                wmma::mma_sync(accS[nn], qf[kk], kf, accS[nn]);
            }
        }
        #pragma unroll
        for (int nn = 0; nn < 4; nn++)
            wmma::store_matrix_sync(&Sw[nn*16], accS[nn], LDS4, wmma::mem_row_major);
        __syncwarp();

        // ---- P = exp(S + ps) (fp16 out), row sums ----
        {
            const float*  srow = &Sw[lrow*LDS4 + lcol];
            const __half* prow = &PSp[(row0 + lrow)*LDK + lcol];
            __half*       orow = &Pw[lrow*LDK + lcol];
            float sm = 0.0f;
            #pragma unroll
            for (int c = 0; c < 32; c += 2) {
                float2 pf = __half22float2(*(const __half2*)&prow[c]);
                float p0 = __expf(srow[c+0] + pf.x);
                float p1 = __expf(srow[c+1] + pf.y);
                sm += p0 + p1;
                *(__half2*)&orow[c] = __floats2half2_rn(p0, p1);
            }
            sm += __shfl_xor_sync(0xffffffffu, sm, 1);
            rl += sm;
        }
        __syncwarp();

        // ---- O += P @ V ----
        #pragma unroll
        for (int kk = 0; kk < 4; kk++) {
            HFragA a;
            wmma::load_matrix_sync(a, &Pw[kk*16], LDK);
            #pragma unroll
            for (int nn = 0; nn < 4; nn++) {
                HFragBr vf;
                wmma::load_matrix_sync(vf, &Vp[(kk*16)*LDK + nn*16], LDK);
                wmma::mma_sync(accO[nn], a, vf, accO[nn]);
            }
        }

        if (t < 15) CPA_WAIT0();
        __syncthreads();   // single barrier: buffer handoff
    }

    // ---- warp-private epilogue: normalize, project vs Wo, atomicAdd ----
    #pragma unroll
    for (int nn = 0; nn < 4; nn++)
        wmma::store_matrix_sync(&Sw[nn*16], accO[nn], LDS4, wmma::mem_row_major);
    __syncwarp();
    {
        const float inv = 1.0f / rl;
        const float* orow = &Sw[lrow*LDS4 + lcol];
        __half* hrow = &Pw[lrow*LDK + lcol];
        #pragma unroll
        for (int c = 0; c < 32; c += 2)
            *(__half2*)&hrow[c] = __floats2half2_rn(orow[c]*inv, orow[c+1]*inv);
    }
    __syncwarp();

    HFragC accR[4];
    #pragma unroll
    for (int nn = 0; nn < 4; nn++) wmma::fill_fragment(accR[nn], 0.0f);
    const __half* wo = g_wo + (size_t)(h*64) * D_;
    #pragma unroll
    for (int kk = 0; kk < 4; kk++) {
        HFragA a;
        wmma::load_matrix_sync(a, &Pw[kk*16], LDK);
        #pragma unroll
        for (int nn = 0; nn < 4; nn++) {
            HFragBr wf;
            wmma::load_matrix_sync(wf, wo + (size_t)(kk*16)*D_ + nn*16, D_);
            wmma::mma_sync(accR[nn], a, wf, accR[nn]);
        }
    }
    __syncwarp();
    #pragma unroll
    for (int nn = 0; nn < 4; nn++)
        wmma::store_matrix_sync(&Sw[nn*16], accR[nn], LDS4, wmma::mem_row_major);
    __syncwarp();
    {
        float* dst = &out[(((size_t)b << 10) + i0 + row0 + lrow) * D_ + lcol];
        const float* src = &Sw[lrow*LDS4 + lcol];
        #pragma unroll
        for (int c = 0; c < 32; c++) atomicAdd(dst + c, src[c]);
    }
}

// ---------------------------------------------------------------------------
extern "C" void kernel_launch(void* const* d_in, const int* in_sizes, int n_in,
                              void* d_out, int out_size)
{
    const float* query = (const float*)d_in[0];
    const float* key   = (const float*)d_in[1];
    const float* value = (const float*)d_in[2];
    const float* pos   = (const float*)d_in[3];
    const float* Wq    = (const float*)d_in[4];
    const float* bq    = (const float*)d_in[5];
    const float* Wk    = (const float*)d_in[6];
    const float* bk    = (const float*)d_in[7];
    const float* Wv    = (const float*)d_in[8];
    const float* bv    = (const float*)d_in[9];
    const float* Wp    = (const float*)d_in[10];
    const float* bp    = (const float*)d_in[11];
    const float* Wo    = (const float*)d_in[12];
    const float* bo    = (const float*)d_in[13];
    float* out = (float*)d_out;

    // Merged prologue: init_out + Wo->fp16 + projections(fp16) + pos(fp16)
    prep_kernel<<<dim3(2976), 256>>>(
        query, key, value, pos, Wq, bq, Wk, bk, Wv, bv, Wp, bp, Wo, bo, out);

    // fp16 WMMA attention + fused output projection
    cudaFuncSetAttribute(attn_wmma, cudaFuncAttributeMaxDynamicSharedMemorySize,
                         (int)sizeof(AttnSmemH));
    attn_wmma<<<dim3(L_/128, H_, B_), 256, sizeof(AttnSmemH)>>>(out);
}